// round 1
// baseline (speedup 1.0000x reference)
#include <cuda_runtime.h>

// Scratch (allocation-free rule: __device__ globals)
__device__ float g_pm[32 * 96 * 96 * 96];      // box3(mov), pad 1  -> [32][96][96][96]
__device__ float g_pf[32 * 100 * 100 * 100];   // box3(fix), pad 3  -> [32][100][100][100]

__device__ __forceinline__ float4 ldg4(const float* p) {
    return __ldg(reinterpret_cast<const float4*>(p));
}

// ---------------------------------------------------------------------------
// Stage 1: 3x3x3 box filter, stride 1, zero padding PAD, output dim O per axis.
// Thread = (c, oy, 4-wide x group); marches oz with sliding row-sum registers:
// out(oz) = rs(oz-PAD) + rs(oz+1-PAD) + rs(oz+2-PAD), one new row-sum per step.
// ---------------------------------------------------------------------------
template<int O, int PAD, int DST>
__global__ __launch_bounds__(256) void box3_kernel(const float* __restrict__ in) {
    constexpr int I  = 96;
    constexpr int XG = O / 4;
    constexpr int TOT = 32 * O * XG;

    const int tid = blockIdx.x * 256 + threadIdx.x;
    if (tid >= TOT) return;

    const int xg = tid % XG;
    const int t2 = tid / XG;
    const int oy = t2 % O;
    const int c  = t2 / O;
    const int bx = xg * 4;

    const float* cin = in + (size_t)c * (I * I * I);
    float* outp = (DST == 0 ? g_pm : g_pf)
                + (size_t)c * (O * O * O) + (size_t)oy * O + bx;

    // Fast path: all 6-wide x windows and vector loads fully in-bounds.
    const bool fast = (PAD == 1) ? (bx >= 4 && bx <= I - 8)
                                 : (bx >= 4 && bx <= I - 4);

    auto rowsum = [&](int zin) -> float4 {
        float4 r = make_float4(0.f, 0.f, 0.f, 0.f);
        if ((unsigned)zin >= (unsigned)I) return r;
        const float* zp = cin + (size_t)zin * (I * I);
#pragma unroll
        for (int t = 0; t < 3; ++t) {
            const int iny = oy + t - PAD;
            if ((unsigned)iny >= (unsigned)I) continue;
            const float* p = zp + iny * I;
            float w0, w1, w2, w3, w4, w5;
            if (fast) {
                if (PAD == 1) {
                    float4 m = ldg4(p + bx);
                    w0 = __ldg(p + bx - 1);
                    w1 = m.x; w2 = m.y; w3 = m.z; w4 = m.w;
                    w5 = __ldg(p + bx + 4);
                } else {
                    float4 a = ldg4(p + bx - 4);
                    float4 b = ldg4(p + bx);
                    w0 = a.y; w1 = a.z; w2 = a.w;
                    w3 = b.x; w4 = b.y; w5 = b.z;
                }
            } else {
                const int s = bx - PAD;
                w0 = ((unsigned)(s + 0) < (unsigned)I) ? __ldg(p + s + 0) : 0.f;
                w1 = ((unsigned)(s + 1) < (unsigned)I) ? __ldg(p + s + 1) : 0.f;
                w2 = ((unsigned)(s + 2) < (unsigned)I) ? __ldg(p + s + 2) : 0.f;
                w3 = ((unsigned)(s + 3) < (unsigned)I) ? __ldg(p + s + 3) : 0.f;
                w4 = ((unsigned)(s + 4) < (unsigned)I) ? __ldg(p + s + 4) : 0.f;
                w5 = ((unsigned)(s + 5) < (unsigned)I) ? __ldg(p + s + 5) : 0.f;
            }
            r.x += w0 + w1 + w2;
            r.y += w1 + w2 + w3;
            r.z += w2 + w3 + w4;
            r.w += w3 + w4 + w5;
        }
        return r;
    };

    float4 rs0 = rowsum(0 - PAD);
    float4 rs1 = rowsum(1 - PAD);
    for (int oz = 0; oz < O; ++oz) {
        float4 rs2 = rowsum(oz + 2 - PAD);
        float4 o = make_float4(rs0.x + rs1.x + rs2.x,
                               rs0.y + rs1.y + rs2.y,
                               rs0.z + rs1.z + rs2.z,
                               rs0.w + rs1.w + rs2.w);
        *reinterpret_cast<float4*>(outp + (size_t)oz * (O * O)) = o;
        rs0 = rs1; rs1 = rs2;
    }
}

// ---------------------------------------------------------------------------
// Stage 2: correlation. Block tile = 4(z) x 4(y) x 32(x) outputs, 128 threads.
// Thread owns a 2x2 (z,y) register block (voxels z0+tz+2a, y0+ty+2b, x0+lane),
// 27 displacement accumulators each (108 total). pf tile [8][8][36] in smem
// per channel; displaced planes shared across the register block -> 12 LDS
// per voxel-channel instead of 27. All pf accesses in-bounds by construction
// (pf is 100^3 = 96 + 2*2*2 exactly).
// ---------------------------------------------------------------------------
__global__ __launch_bounds__(128, 2) void corr_kernel(float* __restrict__ out) {
    __shared__ float pfs[8][8][36];

    const int lane = threadIdx.x & 31;
    const int ty   = (threadIdx.x >> 5) & 1;
    const int tz   = threadIdx.x >> 6;
    const int x0 = blockIdx.x * 32;
    const int y0 = blockIdx.y * 4;
    const int z0 = blockIdx.z * 4;

    float acc[2][2][27];
#pragma unroll
    for (int a = 0; a < 2; ++a)
#pragma unroll
        for (int b = 0; b < 2; ++b)
#pragma unroll
            for (int d = 0; d < 27; ++d) acc[a][b][d] = 0.f;

#pragma unroll 1
    for (int c = 0; c < 32; ++c) {
        __syncthreads();  // protect pfs from previous channel's readers
        const float* pfc = g_pf + (size_t)c * 1000000;
#pragma unroll
        for (int it = 0; it < 5; ++it) {
            const int idx = threadIdx.x + it * 128;   // 576 float4 rows total
            if (idx < 576) {
                const int r = idx / 9, q = idx - r * 9;
                const int zz = r >> 3, yy = r & 7;
                float4 v = ldg4(pfc + ((z0 + zz) * 100 + (y0 + yy)) * 100 + x0 + q * 4);
                *reinterpret_cast<float4*>(&pfs[zz][yy][q * 4]) = v;
            }
        }
        __syncthreads();

        const float* pmc = g_pm + (size_t)c * 884736;
        float pmv[2][2];
#pragma unroll
        for (int a = 0; a < 2; ++a)
#pragma unroll
            for (int b = 0; b < 2; ++b)
                pmv[a][b] = __ldg(pmc + ((z0 + tz + 2 * a) * 96 + (y0 + ty + 2 * b)) * 96
                                  + x0 + lane);

#pragma unroll
        for (int zp = 0; zp < 4; ++zp)
#pragma unroll
            for (int yp = 0; yp < 4; ++yp) {
                const float* bp = &pfs[tz + 2 * zp][ty + 2 * yp][lane];
                const float v0 = bp[0];
                const float v1 = bp[2];
                const float v2 = bp[4];
#pragma unroll
                for (int a = 0; a < 2; ++a) {
                    const int i = zp - a;
                    if (i < 0 || i > 2) continue;
#pragma unroll
                    for (int b = 0; b < 2; ++b) {
                        const int j = yp - b;
                        if (j < 0 || j > 2) continue;
                        const float pv = pmv[a][b];
                        acc[a][b][i * 9 + j * 3 + 0] += pv * v0;
                        acc[a][b][i * 9 + j * 3 + 1] += pv * v1;
                        acc[a][b][i * 9 + j * 3 + 2] += pv * v2;
                    }
                }
            }
    }

    const float inv = 1.0f / 27.0f;
#pragma unroll
    for (int a = 0; a < 2; ++a)
#pragma unroll
        for (int b = 0; b < 2; ++b) {
            const int z = z0 + tz + 2 * a;
            const int y = y0 + ty + 2 * b;
            const int x = x0 + lane;
            const size_t base = (size_t)(z * 96 + y) * 96 + x;
#pragma unroll
            for (int d = 0; d < 27; ++d)
                out[(size_t)d * 884736 + base] = acc[a][b][d] * inv;
        }
}

extern "C" void kernel_launch(void* const* d_in, const int* in_sizes, int n_in,
                              void* d_out, int out_size) {
    const float* mov = (const float*)d_in[0];
    const float* fix = (const float*)d_in[1];
    float* out = (float*)d_out;

    // pm: 32*96*24 = 73728 threads; pf: 32*100*25 = 80000 threads
    box3_kernel<96, 1, 0><<<(73728 + 255) / 256, 256>>>(mov);
    box3_kernel<100, 3, 1><<<(80000 + 255) / 256, 256>>>(fix);

    dim3 cgrid(3, 24, 24);   // x tiles of 32, y/z tiles of 4
    corr_kernel<<<cgrid, 128>>>(out);
}

// round 2
// speedup vs baseline: 1.2135x; 1.2135x over previous
#include <cuda_runtime.h>

// Scratch (allocation-free rule: __device__ globals)
__device__ float g_pm[32 * 96 * 96 * 96];      // box3(mov), pad 1  -> [32][96][96][96]
__device__ float g_pf[32 * 100 * 100 * 100];   // box3(fix), pad 3  -> [32][100][100][100]

__device__ __forceinline__ float4 ldg4(const float* p) {
    return __ldg(reinterpret_cast<const float4*>(p));
}

__device__ __forceinline__ void cp_async16(void* smem_dst, const void* gmem_src) {
    unsigned sa = (unsigned)__cvta_generic_to_shared(smem_dst);
    asm volatile("cp.async.cg.shared.global [%0], [%1], 16;\n" :: "r"(sa), "l"(gmem_src) : "memory");
}
__device__ __forceinline__ void cp_async_commit() {
    asm volatile("cp.async.commit_group;\n" ::: "memory");
}
__device__ __forceinline__ void cp_async_wait0() {
    asm volatile("cp.async.wait_group 0;\n" ::: "memory");
}

// ---------------------------------------------------------------------------
// Stage 1: 3x3x3 box filter, stride 1, zero pad PAD, output dim O per axis.
// Thread = (c, z-chunk, oy, 4-wide x group); marches ZC z-steps with sliding
// row-sum registers. Z-chunking multiplies grid parallelism ~6x vs R1
// (which was latency-bound at occ=23%, DRAM=17%).
// ---------------------------------------------------------------------------
template<int O, int PAD, int DST, int ZC>
__global__ __launch_bounds__(256) void box3_kernel(const float* __restrict__ in) {
    constexpr int I   = 96;
    constexpr int XG  = O / 4;
    constexpr int NCH = (O + ZC - 1) / ZC;
    constexpr int TOT = 32 * O * XG * NCH;

    const int tid = blockIdx.x * 256 + threadIdx.x;
    if (tid >= TOT) return;

    const int xg = tid % XG;
    const int t2 = tid / XG;
    const int oy = t2 % O;
    const int t3 = t2 / O;
    const int zc = t3 % NCH;
    const int c  = t3 / NCH;
    const int bx = xg * 4;
    const int z0 = zc * ZC;
    const int zend = (z0 + ZC < O) ? (z0 + ZC) : O;

    const float* cin = in + (size_t)c * (I * I * I);
    float* outp = (DST == 0 ? g_pm : g_pf)
                + (size_t)c * (O * O * O) + (size_t)oy * O + bx;

    const bool fast = (PAD == 1) ? (bx >= 4 && bx <= I - 8)
                                 : (bx >= 4 && bx <= I - 4);

    auto rowsum = [&](int zin) -> float4 {
        float4 r = make_float4(0.f, 0.f, 0.f, 0.f);
        if ((unsigned)zin >= (unsigned)I) return r;
        const float* zp = cin + (size_t)zin * (I * I);
#pragma unroll
        for (int t = 0; t < 3; ++t) {
            const int iny = oy + t - PAD;
            if ((unsigned)iny >= (unsigned)I) continue;
            const float* p = zp + iny * I;
            float w0, w1, w2, w3, w4, w5;
            if (fast) {
                if (PAD == 1) {
                    float4 m = ldg4(p + bx);
                    w0 = __ldg(p + bx - 1);
                    w1 = m.x; w2 = m.y; w3 = m.z; w4 = m.w;
                    w5 = __ldg(p + bx + 4);
                } else {
                    float4 a = ldg4(p + bx - 4);
                    float4 b = ldg4(p + bx);
                    w0 = a.y; w1 = a.z; w2 = a.w;
                    w3 = b.x; w4 = b.y; w5 = b.z;
                }
            } else {
                const int s = bx - PAD;
                w0 = ((unsigned)(s + 0) < (unsigned)I) ? __ldg(p + s + 0) : 0.f;
                w1 = ((unsigned)(s + 1) < (unsigned)I) ? __ldg(p + s + 1) : 0.f;
                w2 = ((unsigned)(s + 2) < (unsigned)I) ? __ldg(p + s + 2) : 0.f;
                w3 = ((unsigned)(s + 3) < (unsigned)I) ? __ldg(p + s + 3) : 0.f;
                w4 = ((unsigned)(s + 4) < (unsigned)I) ? __ldg(p + s + 4) : 0.f;
                w5 = ((unsigned)(s + 5) < (unsigned)I) ? __ldg(p + s + 5) : 0.f;
            }
            r.x += w0 + w1 + w2;
            r.y += w1 + w2 + w3;
            r.z += w2 + w3 + w4;
            r.w += w3 + w4 + w5;
        }
        return r;
    };

    float4 rs0 = rowsum(z0 - PAD);
    float4 rs1 = rowsum(z0 + 1 - PAD);
    for (int oz = z0; oz < zend; ++oz) {
        float4 rs2 = rowsum(oz + 2 - PAD);
        float4 o = make_float4(rs0.x + rs1.x + rs2.x,
                               rs0.y + rs1.y + rs2.y,
                               rs0.z + rs1.z + rs2.z,
                               rs0.w + rs1.w + rs2.w);
        *reinterpret_cast<float4*>(outp + (size_t)oz * (O * O)) = o;
        rs0 = rs1; rs1 = rs2;
    }
}

// ---------------------------------------------------------------------------
// Stage 2: correlation. Block tile = 4(z) x 4(y) x 32(x) outputs, 128 threads.
// Thread owns a 2x2 (z,y) register block, 27 displacement accumulators each.
// pf tile [8][8][36] per channel, DOUBLE-BUFFERED via cp.async so channel c+1
// loads overlap channel c compute; one barrier per channel.
// ---------------------------------------------------------------------------
__global__ __launch_bounds__(128, 2) void corr_kernel(float* __restrict__ out) {
    __shared__ float pfs[2][8][8][36];

    const int lane = threadIdx.x & 31;
    const int ty   = (threadIdx.x >> 5) & 1;
    const int tz   = threadIdx.x >> 6;
    const int x0 = blockIdx.x * 32;
    const int y0 = blockIdx.y * 4;
    const int z0 = blockIdx.z * 4;

    // Precompute this thread's 5 tile-load slots (576 float4 rows over 128 thr)
    int s_zz[5], s_yy[5], s_q[5];
    bool s_on[5];
#pragma unroll
    for (int it = 0; it < 5; ++it) {
        const int idx = threadIdx.x + it * 128;
        s_on[it] = idx < 576;
        const int r = idx / 9, q = idx - r * 9;
        s_zz[it] = r >> 3; s_yy[it] = r & 7; s_q[it] = q;
    }

    auto issue_tile = [&](int buf, int c) {
        const float* pfc = g_pf + (size_t)c * 1000000;
#pragma unroll
        for (int it = 0; it < 5; ++it) {
            if (s_on[it]) {
                cp_async16(&pfs[buf][s_zz[it]][s_yy[it]][s_q[it] * 4],
                           pfc + ((z0 + s_zz[it]) * 100 + (y0 + s_yy[it])) * 100
                               + x0 + s_q[it] * 4);
            }
        }
        cp_async_commit();
    };

    float acc[2][2][27];
#pragma unroll
    for (int a = 0; a < 2; ++a)
#pragma unroll
        for (int b = 0; b < 2; ++b)
#pragma unroll
            for (int d = 0; d < 27; ++d) acc[a][b][d] = 0.f;

    issue_tile(0, 0);
    cp_async_wait0();
    __syncthreads();

#pragma unroll 1
    for (int c = 0; c < 32; ++c) {
        const int cur = c & 1;
        if (c < 31) issue_tile(cur ^ 1, c + 1);

        const float* pmc = g_pm + (size_t)c * 884736;
        float pmv[2][2];
#pragma unroll
        for (int a = 0; a < 2; ++a)
#pragma unroll
            for (int b = 0; b < 2; ++b)
                pmv[a][b] = __ldg(pmc + ((z0 + tz + 2 * a) * 96 + (y0 + ty + 2 * b)) * 96
                                  + x0 + lane);

#pragma unroll
        for (int zp = 0; zp < 4; ++zp)
#pragma unroll
            for (int yp = 0; yp < 4; ++yp) {
                const float* bp = &pfs[cur][tz + 2 * zp][ty + 2 * yp][lane];
                const float v0 = bp[0];
                const float v1 = bp[2];
                const float v2 = bp[4];
#pragma unroll
                for (int a = 0; a < 2; ++a) {
                    const int i = zp - a;
                    if (i < 0 || i > 2) continue;
#pragma unroll
                    for (int b = 0; b < 2; ++b) {
                        const int j = yp - b;
                        if (j < 0 || j > 2) continue;
                        const float pv = pmv[a][b];
                        acc[a][b][i * 9 + j * 3 + 0] += pv * v0;
                        acc[a][b][i * 9 + j * 3 + 1] += pv * v1;
                        acc[a][b][i * 9 + j * 3 + 2] += pv * v2;
                    }
                }
            }

        if (c < 31) cp_async_wait0();
        __syncthreads();
    }

    const float inv = 1.0f / 27.0f;
#pragma unroll
    for (int a = 0; a < 2; ++a)
#pragma unroll
        for (int b = 0; b < 2; ++b) {
            const int z = z0 + tz + 2 * a;
            const int y = y0 + ty + 2 * b;
            const int x = x0 + lane;
            const size_t base = (size_t)(z * 96 + y) * 96 + x;
#pragma unroll
            for (int d = 0; d < 27; ++d)
                out[(size_t)d * 884736 + base] = acc[a][b][d] * inv;
        }
}

extern "C" void kernel_launch(void* const* d_in, const int* in_sizes, int n_in,
                              void* d_out, int out_size) {
    const float* mov = (const float*)d_in[0];
    const float* fix = (const float*)d_in[1];
    float* out = (float*)d_out;

    // pm: 32*96*24*6 = 442368 threads (1728 blocks)
    box3_kernel<96, 1, 0, 16><<<(442368 + 255) / 256, 256>>>(mov);
    // pf: 32*100*25*5 = 400000 threads (1563 blocks)
    box3_kernel<100, 3, 1, 20><<<(400000 + 255) / 256, 256>>>(fix);

    dim3 cgrid(3, 24, 24);   // x tiles of 32, y/z tiles of 4
    corr_kernel<<<cgrid, 128>>>(out);
}

// round 3
// speedup vs baseline: 1.4526x; 1.1971x over previous
#include <cuda_runtime.h>

// Scratch (allocation-free rule: __device__ globals)
__device__ float g_pm[32 * 96 * 96 * 96];      // box3(mov), pad 1  -> [32][96][96][96]
__device__ float g_pf[32 * 100 * 100 * 100];   // box3(fix), pad 3  -> [32][100][100][100]

__device__ __forceinline__ float4 ldg4(const float* p) {
    return __ldg(reinterpret_cast<const float4*>(p));
}

__device__ __forceinline__ void cp_async16(void* smem_dst, const void* gmem_src) {
    unsigned sa = (unsigned)__cvta_generic_to_shared(smem_dst);
    asm volatile("cp.async.cg.shared.global [%0], [%1], 16;\n" :: "r"(sa), "l"(gmem_src) : "memory");
}
__device__ __forceinline__ void cp_async_commit() {
    asm volatile("cp.async.commit_group;\n" ::: "memory");
}
__device__ __forceinline__ void cp_async_wait0() {
    asm volatile("cp.async.wait_group 0;\n" ::: "memory");
}

// ---------------------------------------------------------------------------
// Stage 1: 3x3x3 box filter, stride 1, zero pad PAD, output dim O per axis.
// Thread = (c, z-chunk, oy-PAIR, 4-wide x group). Produces TWO output y-rows
// from 4 input rows per z-plane step. Horizontal 3-window sums come from ONE
// aligned float4 per row plus warp shuffles (edge lanes use predicated loads)
// -> ~4x fewer L1 wavefronts than R2 (which was L1=77.7% bound).
// All shuffles execute unconditionally; OOB handled by zeroing sources.
// ---------------------------------------------------------------------------
template<int O, int PAD, int DST, int ZC>
__global__ __launch_bounds__(256) void box3_kernel(const float* __restrict__ in) {
    constexpr int I   = 96;
    constexpr int XG  = O / 4;
    constexpr int YP  = O / 2;
    constexpr int NCH = (O + ZC - 1) / ZC;
    constexpr int TOT = 32 * YP * XG * NCH;   // multiple of 32 for both instantiations

    const int tid = blockIdx.x * 256 + threadIdx.x;
    if (tid >= TOT) return;                    // warp-aligned exit

    const int lane = threadIdx.x & 31;
    const int xg = tid % XG;
    int t2 = tid / XG;
    const int oyp = t2 % YP;
    t2 /= YP;
    const int zc = t2 % NCH;
    const int c  = t2 / NCH;
    const int bx = xg * 4;
    const int oy0 = oyp * 2;
    const int z0 = zc * ZC;
    const int zend = (z0 + ZC < O) ? (z0 + ZC) : O;

    const float* cin = in + (size_t)c * (I * I * I);
    float* outp = (DST == 0 ? g_pm : g_pf)
                + (size_t)c * (O * O * O) + (size_t)oy0 * O + bx;

    // Horizontal-window source availability for this lane
    const bool shfl_prev_ok = (lane > 0)  && (xg > 0);
    const bool shfl_next_ok = (lane < 31) && (xg < XG - 1);

    // One z-plane step: compute horizontal 3-sums for 4 rows, combine into
    // the two y-window sums sA (rows 0..2) and sB (rows 1..3).
    auto plane_sums = [&](int zin, float4& sA, float4& sB) {
        const bool zok = ((unsigned)zin < (unsigned)I);
        const float* zp = cin + (size_t)zin * (I * I);
        float4 rv[4];
#pragma unroll
        for (int t = 0; t < 4; ++t) {
            const int r = oy0 - PAD + t;
            const bool rok = zok && ((unsigned)r < (unsigned)I);
            const float* p = zp + r * I;

            float4 v = make_float4(0.f, 0.f, 0.f, 0.f);
            if (PAD == 1) {
                if (rok) v = ldg4(p + bx);                 // bx in [0,92] always
                // w0 = x[bx-1], w5 = x[bx+4]
                float w0 = __shfl_up_sync(0xffffffffu, v.w, 1);
                float w5 = __shfl_down_sync(0xffffffffu, v.x, 1);
                if (!shfl_prev_ok) w0 = (rok && bx > 0)      ? __ldg(p + bx - 1) : 0.f;
                if (!shfl_next_ok) w5 = (rok && bx + 4 < I)  ? __ldg(p + bx + 4) : 0.f;
                rv[t].x = w0 + v.x + v.y;
                rv[t].y = v.x + v.y + v.z;
                rv[t].z = v.y + v.z + v.w;
                rv[t].w = v.z + v.w + w5;
            } else {
                // PAD == 3: windows need prev-vec .y/.z/.w and own .x/.y/.z
                if (rok && bx <= I - 4) v = ldg4(p + bx);   // bx==96 -> stays 0
                float py = __shfl_up_sync(0xffffffffu, v.y, 1);
                float pz = __shfl_up_sync(0xffffffffu, v.z, 1);
                float pw = __shfl_up_sync(0xffffffffu, v.w, 1);
                if (!shfl_prev_ok) {
                    if (rok && bx >= 4) {
                        float4 pvv = ldg4(p + bx - 4);
                        py = pvv.y; pz = pvv.z; pw = pvv.w;
                    } else { py = pz = pw = 0.f; }
                }
                rv[t].x = py + pz + pw;
                rv[t].y = pz + pw + v.x;
                rv[t].z = pw + v.x + v.y;
                rv[t].w = v.x + v.y + v.z;
            }
        }
        sA = make_float4(rv[0].x + rv[1].x + rv[2].x, rv[0].y + rv[1].y + rv[2].y,
                         rv[0].z + rv[1].z + rv[2].z, rv[0].w + rv[1].w + rv[2].w);
        sB = make_float4(rv[1].x + rv[2].x + rv[3].x, rv[1].y + rv[2].y + rv[3].y,
                         rv[1].z + rv[2].z + rv[3].z, rv[1].w + rv[2].w + rv[3].w);
    };

    float4 a0, a1, a2, b0, b1, b2;
    plane_sums(z0 - PAD,     a0, b0);
    plane_sums(z0 + 1 - PAD, a1, b1);
    for (int oz = z0; oz < zend; ++oz) {
        plane_sums(oz + 2 - PAD, a2, b2);
        float4 oA = make_float4(a0.x + a1.x + a2.x, a0.y + a1.y + a2.y,
                                a0.z + a1.z + a2.z, a0.w + a1.w + a2.w);
        float4 oB = make_float4(b0.x + b1.x + b2.x, b0.y + b1.y + b2.y,
                                b0.z + b1.z + b2.z, b0.w + b1.w + b2.w);
        float* op = outp + (size_t)oz * (O * O);
        *reinterpret_cast<float4*>(op)     = oA;
        *reinterpret_cast<float4*>(op + O) = oB;
        a0 = a1; a1 = a2; b0 = b1; b1 = b2;
    }
}

// ---------------------------------------------------------------------------
// Stage 2: correlation. Block tile = 4(z) x 4(y) x 32(x) outputs, 128 threads.
// Thread owns a 2x2 (z,y) register block, 27 displacement accumulators each.
// pf tile [8][8][36] per channel, double-buffered via cp.async. pm values for
// channel c+1 prefetched into registers during channel c compute.
// launch_bounds(128,3): 12 warps/SM (R2 was latency-exposed at 8).
// ---------------------------------------------------------------------------
__global__ __launch_bounds__(128, 3) void corr_kernel(float* __restrict__ out) {
    __shared__ float pfs[2][8][8][36];

    const int lane = threadIdx.x & 31;
    const int ty   = (threadIdx.x >> 5) & 1;
    const int tz   = threadIdx.x >> 6;
    const int x0 = blockIdx.x * 32;
    const int y0 = blockIdx.y * 4;
    const int z0 = blockIdx.z * 4;

    // this thread's 5 tile-load slots (576 float4 rows over 128 threads)
    int s_zz[5], s_yy[5], s_q[5];
    bool s_on[5];
#pragma unroll
    for (int it = 0; it < 5; ++it) {
        const int idx = threadIdx.x + it * 128;
        s_on[it] = idx < 576;
        const int r = idx / 9, q = idx - r * 9;
        s_zz[it] = r >> 3; s_yy[it] = r & 7; s_q[it] = q;
    }

    auto issue_tile = [&](int buf, int c) {
        const float* pfc = g_pf + (size_t)c * 1000000;
#pragma unroll
        for (int it = 0; it < 5; ++it) {
            if (s_on[it]) {
                cp_async16(&pfs[buf][s_zz[it]][s_yy[it]][s_q[it] * 4],
                           pfc + ((z0 + s_zz[it]) * 100 + (y0 + s_yy[it])) * 100
                               + x0 + s_q[it] * 4);
            }
        }
        cp_async_commit();
    };

    // pm addresses for the 2x2 register block
    size_t pm_off[2][2];
#pragma unroll
    for (int a = 0; a < 2; ++a)
#pragma unroll
        for (int b = 0; b < 2; ++b)
            pm_off[a][b] = (size_t)((z0 + tz + 2 * a) * 96 + (y0 + ty + 2 * b)) * 96
                         + x0 + lane;

    float acc[2][2][27];
#pragma unroll
    for (int a = 0; a < 2; ++a)
#pragma unroll
        for (int b = 0; b < 2; ++b)
#pragma unroll
            for (int d = 0; d < 27; ++d) acc[a][b][d] = 0.f;

    issue_tile(0, 0);

    float pmv[2][2];
#pragma unroll
    for (int a = 0; a < 2; ++a)
#pragma unroll
        for (int b = 0; b < 2; ++b)
            pmv[a][b] = __ldg(g_pm + pm_off[a][b]);

    cp_async_wait0();
    __syncthreads();

#pragma unroll 1
    for (int c = 0; c < 32; ++c) {
        const int cur = c & 1;
        float pmn[2][2];
        if (c < 31) {
            issue_tile(cur ^ 1, c + 1);
            const float* pmc = g_pm + (size_t)(c + 1) * 884736;
#pragma unroll
            for (int a = 0; a < 2; ++a)
#pragma unroll
                for (int b = 0; b < 2; ++b)
                    pmn[a][b] = __ldg(pmc + pm_off[a][b]);
        }

#pragma unroll
        for (int zp = 0; zp < 4; ++zp)
#pragma unroll
            for (int yp = 0; yp < 4; ++yp) {
                const float* bp = &pfs[cur][tz + 2 * zp][ty + 2 * yp][lane];
                const float v0 = bp[0];
                const float v1 = bp[2];
                const float v2 = bp[4];
#pragma unroll
                for (int a = 0; a < 2; ++a) {
                    const int i = zp - a;
                    if (i < 0 || i > 2) continue;
#pragma unroll
                    for (int b = 0; b < 2; ++b) {
                        const int j = yp - b;
                        if (j < 0 || j > 2) continue;
                        const float pv = pmv[a][b];
                        acc[a][b][i * 9 + j * 3 + 0] += pv * v0;
                        acc[a][b][i * 9 + j * 3 + 1] += pv * v1;
                        acc[a][b][i * 9 + j * 3 + 2] += pv * v2;
                    }
                }
            }

        if (c < 31) {
            cp_async_wait0();
#pragma unroll
            for (int a = 0; a < 2; ++a)
#pragma unroll
                for (int b = 0; b < 2; ++b)
                    pmv[a][b] = pmn[a][b];
        }
        __syncthreads();
    }

    const float inv = 1.0f / 27.0f;
#pragma unroll
    for (int a = 0; a < 2; ++a)
#pragma unroll
        for (int b = 0; b < 2; ++b) {
            const size_t base = pm_off[a][b];   // same layout as output planes
#pragma unroll
            for (int d = 0; d < 27; ++d)
                out[(size_t)d * 884736 + base] = acc[a][b][d] * inv;
        }
}

extern "C" void kernel_launch(void* const* d_in, const int* in_sizes, int n_in,
                              void* d_out, int out_size) {
    const float* mov = (const float*)d_in[0];
    const float* fix = (const float*)d_in[1];
    float* out = (float*)d_out;

    // box96: 32c * 48 y-pairs * 24 xg * 6 z-chunks = 221184 threads (864 blocks)
    box3_kernel<96, 1, 0, 16><<<864, 256>>>(mov);
    // box100: 32c * 50 y-pairs * 25 xg * 5 z-chunks = 200000 threads (782 blocks)
    box3_kernel<100, 3, 1, 20><<<782, 256>>>(fix);

    dim3 cgrid(3, 24, 24);   // x tiles of 32, y/z tiles of 4
    corr_kernel<<<cgrid, 128>>>(out);
}